// round 12
// baseline (speedup 1.0000x reference)
#include <cuda_runtime.h>
#include <cstdint>

#define T_STEPS 512
#define BATCH   32
#define HID     512
#define LN_EPS  1e-5f
#define NBLK    128          // recurrent grid (64 CTAs per direction)
#define HP      544          // hsh pitch (floats); rows also per-row swizzled
#define WP      516          // Wsh pitch (floats)
#define RTHREADS 512         // recurrent block size (16 warps)

// ---- packed fp32x2 helpers (SASS FFMA2 — ptxas never auto-generates this) ----
#define FMA2(acc, a, b) \
    asm("fma.rn.f32x2 %0, %1, %2, %0;" : "+l"(acc) : "l"(a), "l"(b))

__device__ __forceinline__ float2 unpk(unsigned long long v) {
    float2 r;
    asm("mov.b64 {%0, %1}, %2;" : "=f"(r.x), "=f"(r.y) : "l"(v));
    return r;
}

// ---- acquire/release primitives -------------------------------------------
__device__ __forceinline__ void red_rel_add(unsigned* p, unsigned v) {
    asm volatile("red.release.gpu.global.add.u32 [%0], %1;"
                 :: "l"(p), "r"(v) : "memory");
}
__device__ __forceinline__ unsigned ld_acq(const unsigned* p) {
    unsigned v;
    asm volatile("ld.acquire.gpu.global.u32 %0, [%1];"
                 : "=r"(v) : "l"(p) : "memory");
    return v;
}
#define BAR_NAMED(id, cnt) \
    asm volatile("bar.sync %0, %1;" :: "r"(id), "r"(cnt) : "memory")

// ---------------- scratch (static device globals; no allocation) ----------------
__device__ float    g_ax[(size_t)2 * 512 * 32 * 1536];   // LN(x@Wx+bx) per dir
__device__ float    g_seq[(size_t)2 * 512 * 32 * 512];   // layer-0 outputs
__device__ float    g_h[2 * 2 * 32 * 512];               // [buf][dir][b][k]
__device__ float    g_part[2 * 2 * 32 * 3 * 2 * 64];     // [par][dir][b][g][st][cta]
__device__ unsigned g_barD[64];                          // per-dir bar ctr (dir*32)
__device__ unsigned g_hflag[8 * 32];                     // [(dir*4+quad)*32]

// ============================================================================
// Input GEMM: 128x128x16 fp32, 512 threads, 4x8 microtile via FFMA2. (UNCHANGED)
// ============================================================================
#define BM 128
#define BN 128
#define BK 16

__global__ __launch_bounds__(512)
void gemm_ax_kernel(const float* __restrict__ x,
                    const float* __restrict__ Wx,
                    const float* __restrict__ bx,
                    int layer)
{
    const int dir = blockIdx.z;
    const float* A = (layer == 0) ? x
                                  : (g_seq + (size_t)dir * T_STEPS * BATCH * HID);
    const int wsel = 2 * layer + dir;
    const float* Bw   = Wx + (size_t)wsel * 512 * 1536;
    const float* bias = bx + (size_t)wsel * 1536;
    float* C = g_ax + (size_t)dir * 16384 * 1536;

    const int m0 = blockIdx.y * BM;
    const int n0 = blockIdx.x * BN;

    __shared__ float As2[BK][2 * BM];
    __shared__ float Bs[BK][BN];

    const int tid = threadIdx.x;
    const int arow = tid & 127, akq = tid >> 7;
    const int bkr  = tid >> 5,  bcq = tid & 31;
    const int tx = tid & 15, rg = tid >> 4;

    unsigned long long acc2[4][4];
#pragma unroll
    for (int i = 0; i < 4; ++i)
#pragma unroll
        for (int j = 0; j < 4; ++j) acc2[i][j] = 0ull;

    for (int k0 = 0; k0 < 512; k0 += BK) {
        const float4 av = *(const float4*)(A + (size_t)(m0 + arow) * 512 + k0 + akq * 4);
        const float4 bv = *(const float4*)(Bw + (size_t)(k0 + bkr) * 1536 + n0 + bcq * 4);

        *(float2*)&As2[akq * 4 + 0][2 * arow] = make_float2(av.x, av.x);
        *(float2*)&As2[akq * 4 + 1][2 * arow] = make_float2(av.y, av.y);
        *(float2*)&As2[akq * 4 + 2][2 * arow] = make_float2(av.z, av.z);
        *(float2*)&As2[akq * 4 + 3][2 * arow] = make_float2(av.w, av.w);
        *(float4*)&Bs[bkr][bcq * 4] = bv;
        __syncthreads();

#pragma unroll
        for (int kk = 0; kk < BK; ++kk) {
            const ulonglong2 aL = *(const ulonglong2*)&As2[kk][rg * 8];
            const ulonglong2 aH = *(const ulonglong2*)&As2[kk][rg * 8 + 4];
            const ulonglong2 bL = *(const ulonglong2*)&Bs[kk][tx * 4];
            const ulonglong2 bH = *(const ulonglong2*)&Bs[kk][64 + tx * 4];
            const unsigned long long a[4] = {aL.x, aL.y, aH.x, aH.y};
            const unsigned long long b[4] = {bL.x, bL.y, bH.x, bH.y};
#pragma unroll
            for (int r = 0; r < 4; ++r) {
                FMA2(acc2[r][0], a[r], b[0]);
                FMA2(acc2[r][1], a[r], b[1]);
                FMA2(acc2[r][2], a[r], b[2]);
                FMA2(acc2[r][3], a[r], b[3]);
            }
        }
        __syncthreads();
    }

    const float4 bb0 = *(const float4*)(bias + n0 + tx * 4);
    const float4 bb1 = *(const float4*)(bias + n0 + 64 + tx * 4);
#pragma unroll
    for (int r = 0; r < 4; ++r) {
        const float2 u0 = unpk(acc2[r][0]), u1 = unpk(acc2[r][1]);
        const float2 u2 = unpk(acc2[r][2]), u3 = unpk(acc2[r][3]);
        const int row = m0 + rg * 4 + r;
        float4 o0 = make_float4(u0.x + bb0.x, u0.y + bb0.y, u1.x + bb0.z, u1.y + bb0.w);
        float4 o1 = make_float4(u2.x + bb1.x, u2.y + bb1.y, u3.x + bb1.z, u3.y + bb1.w);
        *(float4*)(C + (size_t)row * 1536 + n0 + tx * 4)      = o0;
        *(float4*)(C + (size_t)row * 1536 + n0 + 64 + tx * 4) = o1;
    }
}

// ============================================================================
// LayerNorm over each 512-wide gate chunk of g_ax (UNCHANGED).
// ============================================================================
__global__ void ln_ax_kernel(const float* __restrict__ gx,
                             const float* __restrict__ bex,
                             int layer)
{
    const int id   = blockIdx.x;
    const int gate = id % 3;
    const int row  = (id / 3) & 16383;
    const int dir  = id / (3 * 16384);
    const int wsel = 2 * layer + dir;

    float* p = g_ax + (size_t)dir * 16384 * 1536 + (size_t)row * 1536 + gate * 512;
    const float* gp = gx  + (size_t)wsel * 1536 + gate * 512;
    const float* bp = bex + (size_t)wsel * 1536 + gate * 512;

    const int tid = threadIdx.x;
    float4 v = *(const float4*)(p + tid * 4);
    float s  = v.x + v.y + v.z + v.w;
    float ss = v.x * v.x + v.y * v.y + v.z * v.z + v.w * v.w;
#pragma unroll
    for (int o = 16; o; o >>= 1) {
        s  += __shfl_xor_sync(0xffffffffu, s,  o);
        ss += __shfl_xor_sync(0xffffffffu, ss, o);
    }
    __shared__ float red[8];
    if ((tid & 31) == 0) { red[tid >> 5] = s; red[4 + (tid >> 5)] = ss; }
    __syncthreads();
    const float ts  = red[0] + red[1] + red[2] + red[3];
    const float tss = red[4] + red[5] + red[6] + red[7];
    const float mu   = ts * (1.f / 512.f);
    const float var  = tss * (1.f / 512.f) - mu * mu;
    const float rstd = rsqrtf(var + LN_EPS);

    const float4 g4 = *(const float4*)(gp + tid * 4);
    const float4 b4 = *(const float4*)(bp + tid * 4);
    float4 o;
    o.x = (v.x - mu) * rstd * g4.x + b4.x;
    o.y = (v.y - mu) * rstd * g4.y + b4.y;
    o.z = (v.z - mu) * rstd * g4.z + b4.z;
    o.w = (v.w - mu) * rstd * g4.w + b4.w;
    *(float4*)(p + tid * 4) = o;
}

// ============================================================================
__global__ void init_scratch_kernel()
{
    const int i = threadIdx.x;
    for (int k = i; k < 64; k += blockDim.x) g_barD[k] = 0u;
    for (int k = i; k < 8 * 32; k += blockDim.x) g_hflag[k] = 0u;
}

// ============================================================================
// Per-direction grid barrier (acquire/release, proven R10 design).
// ============================================================================
__device__ __forceinline__ void bar_dir(unsigned* ctr, unsigned& target)
{
    __syncthreads();
    if (threadIdx.x == 0) {
        red_rel_add(ctr, 1u);
        target += 64u;
        while (ld_acq(ctr) < target) { }
    }
    __syncthreads();
}

// h row pointer with per-row bank swizzle.
#define HROW(hsh, b) ((hsh) + (b) * HP + ((((b) >> 1) & 7) << 2))

// ============================================================================
// Persistent recurrent kernel — single grid barrier per step.
// h exchange via double-buffered g_h + per-quad release flags: phase-A warp
// group q loads only its own h quarter when its 16 producer CTAs have flagged.
// Warps 8-15 skip phase B and prefetch their quarters early.
// ============================================================================
__global__ __launch_bounds__(RTHREADS)
void recurrent_kernel(const float* __restrict__ Wh,
                      const float* __restrict__ bh,
                      const float* __restrict__ gh,
                      const float* __restrict__ beh,
                      const float* __restrict__ h0,
                      float* __restrict__ out,
                      int layer, int write_hid)
{
    extern __shared__ float sm[];
    float* Wsh  = sm;                          // [24][WP] col-major   12384 f
    float* hsh  = Wsh + 24 * WP;               // [32][HP] swizzled    17408 f
    float* raws = hsh + 32 * HP;               // 4 x [32][25] k-quads  3200 f
    float* bhs  = raws + 4 * 800;              // 24 f
    float* ghs  = bhs + 24;                    // 24 f
    float* behs = ghs + 24;                    // 24 f

    const int tid = threadIdx.x;
    const int cta = blockIdx.x;
    const int dir = cta >> 6;                  // 0 = fwd, 1 = bwd
    const int ctaLoc = cta & 63;
    const int j0  = ctaLoc * 8;
    const int wsel = 2 * layer + dir;
    unsigned* ctr = g_barD + dir * 32;

    // ---- one-time loads ----
    const float* Whd = Wh + (size_t)wsel * 512 * 1536;
    for (int i = tid; i < 24 * 512; i += RTHREADS) {
        const int c = i >> 9, k = i & 511;
        const int col = ((c >> 3) << 9) + j0 + (c & 7);
        Wsh[c * WP + k] = Whd[(size_t)k * 1536 + col];
    }
    if (tid < 24) {
        const int col = ((tid >> 3) << 9) + j0 + (tid & 7);
        bhs[tid]  = bh [(size_t)wsel * 1536 + col];
        ghs[tid]  = gh [(size_t)wsel * 1536 + col];
        behs[tid] = beh[(size_t)wsel * 1536 + col];
    }
    for (int i = tid; i < 32 * 128; i += RTHREADS) {
        const int b = i >> 7, q = i & 127;
        *(float4*)(HROW(hsh, b) + q * 4) =
            *(const float4*)(h0 + (size_t)wsel * 32 * 512 + b * 512 + q * 4);
    }
    __syncthreads();

    unsigned target = 0;
    // phase-A map: 16 warps = colHalf(2) x bHalf(2) x kQuad(4)
    const int warp = tid >> 5, lane = tid & 31;
    const int colHalf = warp & 1, bHalf = (warp >> 1) & 1, kQuad = warp >> 2;
    const int cgrp = lane & 3, bpair = lane >> 2;
    const int c0  = colHalf * 12 + cgrp * 3;
    const int bA0 = bHalf * 16 + bpair * 2;
    const int kof = kQuad * 128;
    float* rawK = raws + kQuad * 800;
    unsigned* hf = g_hflag + (dir * 4 + kQuad) * 32;   // flag this group waits on
    unsigned* hfOwn = g_hflag + (dir * 4 + (ctaLoc >> 4)) * 32; // flag CTA signals
    const int gtid = tid & 127;                // id within kQuad group
    // phase-B map (first 256 threads)
    const int jB = tid & 7, bB = tid >> 3;

    const float* hr0 = HROW(hsh, bA0)     + kof;
    const float* hr1 = HROW(hsh, bA0 + 1) + kof;
    const float* w0 = Wsh + c0 * WP + kof;
    const float* w1 = w0 + WP;
    const float* w2 = w1 + WP;

    for (int s = 0; s < T_STEPS; ++s) {
        const int tin = dir ? (T_STEPS - 1 - s) : s;
        const int par = s & 1;

        // ---- A: prefetch ax + per-quad h reload ---------------------------
        float axr = 0.f, axz = 0.f, axn = 0.f;
        if (tid < 256) {
            const float* axp = g_ax + (((size_t)dir * T_STEPS + tin) * 32 + bB) * 1536
                                    + j0 + jB;
            axr = __ldg(axp);
            axz = __ldg(axp + 512);
            axn = __ldg(axp + 1024);
        }
        if (s > 0) {
            if (lane == 0) {
                const unsigned want = 16u * (unsigned)s;
                while (ld_acq(hf) < want) { }
            }
            __syncwarp();
            const float* src = g_h + (size_t)((((s - 1) & 1) * 2 + dir) * 32) * 512;
#pragma unroll
            for (int r = 0; r < 8; ++r) {
                const int i = gtid + r * 128;
                const int b = i >> 5, kq = i & 31;
                const float4 v = __ldcg((const float4*)(src + b * 512 + kof + kq * 4));
                *(float4*)(HROW(hsh, b) + kof + kq * 4) = v;
            }
        }
        BAR_NAMED(kQuad + 1, 128);   // h quarter ready for this group

        // ---- C: Phase A: 2-batch x 3-col x 128-k GEMM via FFMA2 -----------
        {
            unsigned long long a00x=0,a00y=0,a01x=0,a01y=0;
            unsigned long long a10x=0,a10y=0,a11x=0,a11y=0;
            unsigned long long a20x=0,a20y=0,a21x=0,a21y=0;
#pragma unroll 4
            for (int k = 0; k < 128; k += 4) {
                const ulonglong2 ha = *(const ulonglong2*)(hr0 + k);
                const ulonglong2 hb = *(const ulonglong2*)(hr1 + k);
                const ulonglong2 wa = *(const ulonglong2*)(w0 + k);
                const ulonglong2 wb = *(const ulonglong2*)(w1 + k);
                const ulonglong2 wc = *(const ulonglong2*)(w2 + k);
                FMA2(a00x, ha.x, wa.x); FMA2(a00y, ha.y, wa.y);
                FMA2(a01x, hb.x, wa.x); FMA2(a01y, hb.y, wa.y);
                FMA2(a10x, ha.x, wb.x); FMA2(a10y, ha.y, wb.y);
                FMA2(a11x, hb.x, wb.x); FMA2(a11y, hb.y, wb.y);
                FMA2(a20x, ha.x, wc.x); FMA2(a20y, ha.y, wc.y);
                FMA2(a21x, hb.x, wc.x); FMA2(a21y, hb.y, wc.y);
            }
            float2 u, v;
            float* rpa = rawK + bA0 * 25 + c0;
            float* rpb = rawK + (bA0 + 1) * 25 + c0;
            u = unpk(a00x); v = unpk(a00y); rpa[0] = u.x + u.y + v.x + v.y;
            u = unpk(a10x); v = unpk(a10y); rpa[1] = u.x + u.y + v.x + v.y;
            u = unpk(a20x); v = unpk(a20y); rpa[2] = u.x + u.y + v.x + v.y;
            u = unpk(a01x); v = unpk(a01y); rpb[0] = u.x + u.y + v.x + v.y;
            u = unpk(a11x); v = unpk(a11y); rpb[1] = u.x + u.y + v.x + v.y;
            u = unpk(a21x); v = unpk(a21y); rpb[2] = u.x + u.y + v.x + v.y;
        }
        __syncthreads();   // raws complete, hsh(s-1) stable below

        // ---- E: CTA-local pre-barrier work --------------------------------
        float vr = 0.f, vz = 0.f, vn = 0.f, hp = 0.f;
        if (tid < 256) {
            const int off = bB * 25;
            vr = raws[off + jB]        + raws[800 + off + jB]
               + raws[1600 + off + jB] + raws[2400 + off + jB] + bhs[jB];
            vz = raws[off + 8 + jB]        + raws[800 + off + 8 + jB]
               + raws[1600 + off + 8 + jB] + raws[2400 + off + 8 + jB] + bhs[8 + jB];
            vn = raws[off + 16 + jB]        + raws[800 + off + 16 + jB]
               + raws[1600 + off + 16 + jB] + raws[2400 + off + 16 + jB] + bhs[16 + jB];
            hp = HROW(hsh, bB)[j0 + jB];
        }
        if (tid < 96) {
            const int g = tid >> 5, b = tid & 31;
            const int off = b * 25 + g * 8;
            const float* bb = bhs + g * 8;
            float sum = 0.f, sq = 0.f;
#pragma unroll
            for (int i = 0; i < 8; ++i) {
                const float v = raws[off + i] + raws[800 + off + i]
                              + raws[1600 + off + i] + raws[2400 + off + i]
                              + bb[i];
                sum += v; sq += v * v;
            }
            const int base = ((((par * 2 + dir) * 32 + b) * 3 + g) * 2) * 64 + ctaLoc;
            g_part[base]      = sum;
            g_part[base + 64] = sq;
        }
        bar_dir(ctr, target);   // stats complete (own dir only)

        // ---- G: Phase B (256 threads): reduce partials, gates, h_new ------
        if (tid < 256) {
            const float* pb = g_part + (size_t)((par * 2 + dir) * 32 + bB) * 384
                            + jB * 8;
            float tot[6];
#pragma unroll
            for (int g = 0; g < 3; ++g)
#pragma unroll
                for (int st = 0; st < 2; ++st) {
                    const float4 u0 = __ldcg((const float4*)(pb + g * 128 + st * 64));
                    const float4 u1 = __ldcg((const float4*)(pb + g * 128 + st * 64 + 4));
                    tot[g * 2 + st] = u0.x + u0.y + u0.z + u0.w
                                    + u1.x + u1.y + u1.z + u1.w;
                }
#pragma unroll
            for (int o = 1; o < 8; o <<= 1)
#pragma unroll
                for (int t = 0; t < 6; ++t)
                    tot[t] += __shfl_xor_sync(0xffffffffu, tot[t], o);

            const float mu0 = tot[0] * (1.f / 512.f);
            const float mu1 = tot[2] * (1.f / 512.f);
            const float mu2 = tot[4] * (1.f / 512.f);
            const float r0 = rsqrtf(tot[1] * (1.f / 512.f) - mu0 * mu0 + LN_EPS);
            const float r1 = rsqrtf(tot[3] * (1.f / 512.f) - mu1 * mu1 + LN_EPS);
            const float r2 = rsqrtf(tot[5] * (1.f / 512.f) - mu2 * mu2 + LN_EPS);

            const float ahr = (vr - mu0) * r0 * ghs[jB]      + behs[jB];
            const float ahz = (vz - mu1) * r1 * ghs[8 + jB]  + behs[8 + jB];
            const float ahn = (vn - mu2) * r2 * ghs[16 + jB] + behs[16 + jB];

            const float r = 1.f / (1.f + __expf(-(axr + ahr)));
            const float z = 1.f / (1.f + __expf(-(axz + ahz)));
            const float n = tanhf(axn + r * ahn);
            const float hn = fmaf(z, hp - n, n);   // (1-z)*n + z*h

            g_h[(size_t)((par * 2 + dir) * 32 + bB) * 512 + j0 + jB] = hn;
            if (layer == 0) {
                g_seq[(size_t)dir * T_STEPS * 32 * 512
                      + ((size_t)tin * 32 + bB) * 512 + j0 + jB] = hn;
            } else {
                out[((size_t)tin * 32 + bB) * 1024 + dir * 512 + j0 + jB] = hn;
            }
            if (write_hid && s == T_STEPS - 1)
                out[(size_t)16777216 + ((size_t)wsel * 32 + bB) * 512 + j0 + jB] = hn;

            // ---- H: publish own h slice (warps 0-7 only) ------------------
            BAR_NAMED(7, 256);
            if (tid == 0) red_rel_add(hfOwn, 1u);
        }
    }
}

// ============================================================================
#define RS_BYTES ((24*WP + 32*HP + 4*800 + 24*3) * 4)

extern "C" void kernel_launch(void* const* d_in, const int* in_sizes, int n_in,
                              void* d_out, int out_size)
{
    const float* x   = (const float*)d_in[0];
    const float* h0  = (const float*)d_in[1];
    const float* Wx  = (const float*)d_in[2];
    const float* Wh  = (const float*)d_in[3];
    const float* bx  = (const float*)d_in[4];
    const float* bh  = (const float*)d_in[5];
    const float* gx  = (const float*)d_in[6];
    const float* bex = (const float*)d_in[7];
    const float* gh  = (const float*)d_in[8];
    const float* beh = (const float*)d_in[9];
    float* out = (float*)d_out;

    const int write_hid = (out_size >= 16777216 + 4 * 32 * 512) ? 1 : 0;

    cudaFuncSetAttribute(recurrent_kernel,
                         cudaFuncAttributeMaxDynamicSharedMemorySize, RS_BYTES);

    for (int layer = 0; layer < 2; ++layer) {
        dim3 gg(1536 / BN, 16384 / BM, 2);
        gemm_ax_kernel<<<gg, 512>>>(x, Wx, bx, layer);
        ln_ax_kernel<<<2 * 16384 * 3, 128>>>(gx, bex, layer);
        init_scratch_kernel<<<1, 256>>>();
        recurrent_kernel<<<NBLK, RTHREADS, RS_BYTES>>>(Wh, bh, gh, beh, h0, out,
                                                       layer, write_hid);
    }
}

// round 13
// speedup vs baseline: 1.4733x; 1.4733x over previous
#include <cuda_runtime.h>
#include <cstdint>

#define T_STEPS 512
#define BATCH   32
#define HID     512
#define LN_EPS  1e-5f
#define NBLK    128          // recurrent grid (64 CTAs per direction)
#define HP      544          // hsh pitch (floats); rows also per-row swizzled
#define WP      516          // Wsh pitch (floats)

// ---- packed fp32x2 helpers (SASS FFMA2 — ptxas never auto-generates this) ----
#define FMA2(acc, a, b) \
    asm("fma.rn.f32x2 %0, %1, %2, %0;" : "+l"(acc) : "l"(a), "l"(b))

__device__ __forceinline__ float2 unpk(unsigned long long v) {
    float2 r;
    asm("mov.b64 {%0, %1}, %2;" : "=f"(r.x), "=f"(r.y) : "l"(v));
    return r;
}

// ---- acquire/release barrier primitives (no per-thread fences) --------------
__device__ __forceinline__ void red_rel_add(unsigned* p, unsigned v) {
    asm volatile("red.release.gpu.global.add.u32 [%0], %1;"
                 :: "l"(p), "r"(v) : "memory");
}
__device__ __forceinline__ unsigned ld_acq(const unsigned* p) {
    unsigned v;
    asm volatile("ld.acquire.gpu.global.u32 %0, [%1];"
                 : "=r"(v) : "l"(p) : "memory");
    return v;
}

// ---- cp.async (LDGSTS): register-free L2->SMEM copy for the h reload --------
#define CP_ASYNC16(dst_u32, src_ptr) \
    asm volatile("cp.async.cg.shared.global [%0], [%1], 16;" \
                 :: "r"(dst_u32), "l"(src_ptr) : "memory")
#define CP_COMMIT() asm volatile("cp.async.commit_group;" ::: "memory")
#define CP_WAIT0()  asm volatile("cp.async.wait_group 0;" ::: "memory")

// ---------------- scratch (static device globals; no allocation) ----------------
__device__ float    g_ax[(size_t)2 * 512 * 32 * 1536];   // LN(x@Wx+bx) per dir
__device__ float    g_seq[(size_t)2 * 512 * 32 * 512];   // layer-0 outputs (fwd, bwd)
__device__ float    g_h[2 * 32 * 512];                   // current hidden state per dir
__device__ float    g_part[2 * 32 * 3 * 2 * 64];         // [dir][b][g][stat][cta]
__device__ unsigned g_barD[64];                          // per-dir counters (idx dir*32)

// ============================================================================
// Input GEMM: 128x128x16 fp32, 512 threads, 4x8 microtile via FFMA2. (UNCHANGED)
// ============================================================================
#define BM 128
#define BN 128
#define BK 16

__global__ __launch_bounds__(512)
void gemm_ax_kernel(const float* __restrict__ x,
                    const float* __restrict__ Wx,
                    const float* __restrict__ bx,
                    int layer)
{
    const int dir = blockIdx.z;
    const float* A = (layer == 0) ? x
                                  : (g_seq + (size_t)dir * T_STEPS * BATCH * HID);
    const int wsel = 2 * layer + dir;
    const float* Bw   = Wx + (size_t)wsel * 512 * 1536;
    const float* bias = bx + (size_t)wsel * 1536;
    float* C = g_ax + (size_t)dir * 16384 * 1536;

    const int m0 = blockIdx.y * BM;
    const int n0 = blockIdx.x * BN;

    __shared__ float As2[BK][2 * BM];
    __shared__ float Bs[BK][BN];

    const int tid = threadIdx.x;
    const int arow = tid & 127, akq = tid >> 7;
    const int bkr  = tid >> 5,  bcq = tid & 31;
    const int tx = tid & 15, rg = tid >> 4;

    unsigned long long acc2[4][4];
#pragma unroll
    for (int i = 0; i < 4; ++i)
#pragma unroll
        for (int j = 0; j < 4; ++j) acc2[i][j] = 0ull;

    for (int k0 = 0; k0 < 512; k0 += BK) {
        const float4 av = *(const float4*)(A + (size_t)(m0 + arow) * 512 + k0 + akq * 4);
        const float4 bv = *(const float4*)(Bw + (size_t)(k0 + bkr) * 1536 + n0 + bcq * 4);

        *(float2*)&As2[akq * 4 + 0][2 * arow] = make_float2(av.x, av.x);
        *(float2*)&As2[akq * 4 + 1][2 * arow] = make_float2(av.y, av.y);
        *(float2*)&As2[akq * 4 + 2][2 * arow] = make_float2(av.z, av.z);
        *(float2*)&As2[akq * 4 + 3][2 * arow] = make_float2(av.w, av.w);
        *(float4*)&Bs[bkr][bcq * 4] = bv;
        __syncthreads();

#pragma unroll
        for (int kk = 0; kk < BK; ++kk) {
            const ulonglong2 aL = *(const ulonglong2*)&As2[kk][rg * 8];
            const ulonglong2 aH = *(const ulonglong2*)&As2[kk][rg * 8 + 4];
            const ulonglong2 bL = *(const ulonglong2*)&Bs[kk][tx * 4];
            const ulonglong2 bH = *(const ulonglong2*)&Bs[kk][64 + tx * 4];
            const unsigned long long a[4] = {aL.x, aL.y, aH.x, aH.y};
            const unsigned long long b[4] = {bL.x, bL.y, bH.x, bH.y};
#pragma unroll
            for (int r = 0; r < 4; ++r) {
                FMA2(acc2[r][0], a[r], b[0]);
                FMA2(acc2[r][1], a[r], b[1]);
                FMA2(acc2[r][2], a[r], b[2]);
                FMA2(acc2[r][3], a[r], b[3]);
            }
        }
        __syncthreads();
    }

    const float4 bb0 = *(const float4*)(bias + n0 + tx * 4);
    const float4 bb1 = *(const float4*)(bias + n0 + 64 + tx * 4);
#pragma unroll
    for (int r = 0; r < 4; ++r) {
        const float2 u0 = unpk(acc2[r][0]), u1 = unpk(acc2[r][1]);
        const float2 u2 = unpk(acc2[r][2]), u3 = unpk(acc2[r][3]);
        const int row = m0 + rg * 4 + r;
        float4 o0 = make_float4(u0.x + bb0.x, u0.y + bb0.y, u1.x + bb0.z, u1.y + bb0.w);
        float4 o1 = make_float4(u2.x + bb1.x, u2.y + bb1.y, u3.x + bb1.z, u3.y + bb1.w);
        *(float4*)(C + (size_t)row * 1536 + n0 + tx * 4)      = o0;
        *(float4*)(C + (size_t)row * 1536 + n0 + 64 + tx * 4) = o1;
    }
}

// ============================================================================
// LayerNorm over each 512-wide gate chunk of g_ax (UNCHANGED).
// ============================================================================
__global__ void ln_ax_kernel(const float* __restrict__ gx,
                             const float* __restrict__ bex,
                             int layer)
{
    const int id   = blockIdx.x;
    const int gate = id % 3;
    const int row  = (id / 3) & 16383;
    const int dir  = id / (3 * 16384);
    const int wsel = 2 * layer + dir;

    float* p = g_ax + (size_t)dir * 16384 * 1536 + (size_t)row * 1536 + gate * 512;
    const float* gp = gx  + (size_t)wsel * 1536 + gate * 512;
    const float* bp = bex + (size_t)wsel * 1536 + gate * 512;

    const int tid = threadIdx.x;
    float4 v = *(const float4*)(p + tid * 4);
    float s  = v.x + v.y + v.z + v.w;
    float ss = v.x * v.x + v.y * v.y + v.z * v.z + v.w * v.w;
#pragma unroll
    for (int o = 16; o; o >>= 1) {
        s  += __shfl_xor_sync(0xffffffffu, s,  o);
        ss += __shfl_xor_sync(0xffffffffu, ss, o);
    }
    __shared__ float red[8];
    if ((tid & 31) == 0) { red[tid >> 5] = s; red[4 + (tid >> 5)] = ss; }
    __syncthreads();
    const float ts  = red[0] + red[1] + red[2] + red[3];
    const float tss = red[4] + red[5] + red[6] + red[7];
    const float mu   = ts * (1.f / 512.f);
    const float var  = tss * (1.f / 512.f) - mu * mu;
    const float rstd = rsqrtf(var + LN_EPS);

    const float4 g4 = *(const float4*)(gp + tid * 4);
    const float4 b4 = *(const float4*)(bp + tid * 4);
    float4 o;
    o.x = (v.x - mu) * rstd * g4.x + b4.x;
    o.y = (v.y - mu) * rstd * g4.y + b4.y;
    o.z = (v.z - mu) * rstd * g4.z + b4.z;
    o.w = (v.w - mu) * rstd * g4.w + b4.w;
    *(float4*)(p + tid * 4) = o;
}

// ============================================================================
__global__ void init_scratch_kernel()
{
    const int i = threadIdx.x;
    for (int k = i; k < 64; k += blockDim.x) g_barD[k] = 0u;
}

// ============================================================================
// Per-direction grid barrier (acquire/release, proven R10 design).
// ============================================================================
__device__ __forceinline__ void bar_dir(unsigned* ctr, unsigned& target)
{
    __syncthreads();                     // all CTA writes done (cta-scope rel)
    if (threadIdx.x == 0) {
        red_rel_add(ctr, 1u);            // release: publishes CTA's writes
        target += 64u;
        while (ld_acq(ctr) < target) { } // acquire: imports peers' writes
    }
    __syncthreads();                     // broadcast acquire to whole CTA
}

// h row pointer with per-row bank swizzle.
#define HROW(hsh, b) ((hsh) + (b) * HP + ((((b) >> 1) & 7) << 2))

// ============================================================================
// Persistent recurrent kernel — exact R10 structure (best so far), with the
// h reload converted to cp.async.cg (register-free, single exposed latency).
// ============================================================================
__global__ __launch_bounds__(256)
void recurrent_kernel(const float* __restrict__ Wh,
                      const float* __restrict__ bh,
                      const float* __restrict__ gh,
                      const float* __restrict__ beh,
                      const float* __restrict__ h0,
                      float* __restrict__ out,
                      int layer, int write_hid)
{
    extern __shared__ float sm[];
    float* Wsh  = sm;                          // [24][WP] col-major   12384 f
    float* hsh  = Wsh + 24 * WP;               // [32][HP] swizzled    17408 f
    float* raw0 = hsh + 32 * HP;               // [32][25] k-half 0      800 f
    float* raw1 = raw0 + 800;                  // [32][25] k-half 1      800 f
    float* bhs  = raw1 + 800;                  // 24 f
    float* ghs  = bhs + 24;                    // 24 f
    float* behs = ghs + 24;                    // 24 f

    const int tid = threadIdx.x;
    const int cta = blockIdx.x;
    const int dir = cta >> 6;                  // 0 = fwd, 1 = bwd
    const int ctaLoc = cta & 63;
    const int j0  = ctaLoc * 8;
    const int wsel = 2 * layer + dir;
    unsigned* ctr = g_barD + dir * 32;         // separate 128B lines per dir

    // ---- one-time loads ----
    const float* Whd = Wh + (size_t)wsel * 512 * 1536;
    for (int i = tid; i < 24 * 512; i += 256) {
        const int c = i >> 9, k = i & 511;
        const int col = ((c >> 3) << 9) + j0 + (c & 7);
        Wsh[c * WP + k] = Whd[(size_t)k * 1536 + col];
    }
    if (tid < 24) {
        const int col = ((tid >> 3) << 9) + j0 + (tid & 7);
        bhs[tid]  = bh [(size_t)wsel * 1536 + col];
        ghs[tid]  = gh [(size_t)wsel * 1536 + col];
        behs[tid] = beh[(size_t)wsel * 1536 + col];
    }
    for (int i = tid; i < 32 * 128; i += 256) {
        const int b = i >> 7, q = i & 127;
        *(float4*)(HROW(hsh, b) + q * 4) =
            *(const float4*)(h0 + (size_t)wsel * 32 * 512 + b * 512 + q * 4);
    }
    __syncthreads();

    unsigned target = 0;
    // phase-A map: warp = (colHalf, bHalf, kHalf); 3 cols x 2 batches x 256 k
    const int warp = tid >> 5, lane = tid & 31;
    const int colHalf = warp & 1, bHalf = (warp >> 1) & 1, kHalf = warp >> 2;
    const int cgrp = lane & 3, bpair = lane >> 2;
    const int c0  = colHalf * 12 + cgrp * 3;   // 3 cols
    const int bA0 = bHalf * 16 + bpair * 2;    // 2 batches
    const int kof = kHalf * 256;
    float* rawK = kHalf ? raw1 : raw0;
    // phase-B map
    const int jB = tid & 7, bB = tid >> 3;

    const float* hr0 = HROW(hsh, bA0)     + kof;
    const float* hr1 = HROW(hsh, bA0 + 1) + kof;
    const float* w0 = Wsh + c0 * WP + kof;
    const float* w1 = w0 + WP;
    const float* w2 = w1 + WP;

    // precompute SMEM byte addresses for the cp.async h reload (16 per thread)
    unsigned hdst[16];
    const float* hgsrc[16];
    {
        const float* hg = g_h + dir * 32 * 512;
#pragma unroll
        for (int r = 0; r < 16; ++r) {
            const int i = tid + r * 256;
            const int b = i >> 7, q = i & 127;
            hdst[r]  = (unsigned)__cvta_generic_to_shared(HROW(hsh, b) + q * 4);
            hgsrc[r] = hg + b * 512 + q * 4;
        }
    }

    for (int s = 0; s < T_STEPS; ++s) {
        const int tin = dir ? (T_STEPS - 1 - s) : s;

        // prefetch ax for phase B (latency hides under phase-A GEMM)
        const float* axp = g_ax + (((size_t)dir * T_STEPS + tin) * 32 + bB) * 1536
                                + j0 + jB;
        const float axr = __ldg(axp);
        const float axz = __ldg(axp + 512);
        const float axn = __ldg(axp + 1024);

        // -------- Phase A: 2-batch x 3-col x 256-k GEMM via FFMA2 -----------
        {
            unsigned long long a00x=0,a00y=0,a01x=0,a01y=0;
            unsigned long long a10x=0,a10y=0,a11x=0,a11y=0;
            unsigned long long a20x=0,a20y=0,a21x=0,a21y=0;
#pragma unroll 8
            for (int k = 0; k < 256; k += 4) {
                const ulonglong2 ha = *(const ulonglong2*)(hr0 + k);
                const ulonglong2 hb = *(const ulonglong2*)(hr1 + k);
                const ulonglong2 wa = *(const ulonglong2*)(w0 + k);
                const ulonglong2 wb = *(const ulonglong2*)(w1 + k);
                const ulonglong2 wc = *(const ulonglong2*)(w2 + k);
                FMA2(a00x, ha.x, wa.x); FMA2(a00y, ha.y, wa.y);
                FMA2(a01x, hb.x, wa.x); FMA2(a01y, hb.y, wa.y);
                FMA2(a10x, ha.x, wb.x); FMA2(a10y, ha.y, wb.y);
                FMA2(a11x, hb.x, wb.x); FMA2(a11y, hb.y, wb.y);
                FMA2(a20x, ha.x, wc.x); FMA2(a20y, ha.y, wc.y);
                FMA2(a21x, hb.x, wc.x); FMA2(a21y, hb.y, wc.y);
            }
            float2 u, v;
            float* rpa = rawK + bA0 * 25 + c0;
            float* rpb = rawK + (bA0 + 1) * 25 + c0;
            u = unpk(a00x); v = unpk(a00y); rpa[0] = u.x + u.y + v.x + v.y;
            u = unpk(a10x); v = unpk(a10y); rpa[1] = u.x + u.y + v.x + v.y;
            u = unpk(a20x); v = unpk(a20y); rpa[2] = u.x + u.y + v.x + v.y;
            u = unpk(a01x); v = unpk(a01y); rpb[0] = u.x + u.y + v.x + v.y;
            u = unpk(a11x); v = unpk(a11y); rpb[1] = u.x + u.y + v.x + v.y;
            u = unpk(a21x); v = unpk(a21y); rpb[2] = u.x + u.y + v.x + v.y;
        }
        __syncthreads();

        // ---- LN stats partials: 96 threads, plain stores (no atomics) ------
        if (tid < 96) {
            const int g = tid >> 5, b = tid & 31;
            const float* r0 = raw0 + b * 25 + g * 8;
            const float* r1 = raw1 + b * 25 + g * 8;
            const float* bb = bhs + g * 8;
            float sum = 0.f, sq = 0.f;
#pragma unroll
            for (int i = 0; i < 8; ++i) {
                const float v = r0[i] + r1[i] + bb[i];
                sum += v; sq += v * v;
            }
            const int base = (((dir * 32 + b) * 3 + g) * 2) * 64 + ctaLoc;
            g_part[base]      = sum;
            g_part[base + 64] = sq;
        }
        bar_dir(ctr, target);   // stats complete (own dir only)

        // -------- Phase B: reduce partials, gates, h_new --------------------
        {
            const float* pb = g_part + (size_t)(dir * 32 + bB) * 384 + jB * 8;
            float tot[6];
#pragma unroll
            for (int g = 0; g < 3; ++g)
#pragma unroll
                for (int st = 0; st < 2; ++st) {
                    const float4 u0 = __ldcg((const float4*)(pb + g * 128 + st * 64));
                    const float4 u1 = __ldcg((const float4*)(pb + g * 128 + st * 64 + 4));
                    tot[g * 2 + st] = u0.x + u0.y + u0.z + u0.w
                                    + u1.x + u1.y + u1.z + u1.w;
                }
#pragma unroll
            for (int o = 1; o < 8; o <<= 1)
#pragma unroll
                for (int t = 0; t < 6; ++t)
                    tot[t] += __shfl_xor_sync(0xffffffffu, tot[t], o);

            const float mu0 = tot[0] * (1.f / 512.f);
            const float mu1 = tot[2] * (1.f / 512.f);
            const float mu2 = tot[4] * (1.f / 512.f);
            const float r0 = rsqrtf(tot[1] * (1.f / 512.f) - mu0 * mu0 + LN_EPS);
            const float r1 = rsqrtf(tot[3] * (1.f / 512.f) - mu1 * mu1 + LN_EPS);
            const float r2 = rsqrtf(tot[5] * (1.f / 512.f) - mu2 * mu2 + LN_EPS);

            const float vr = raw0[bB * 25 + jB]      + raw1[bB * 25 + jB]      + bhs[jB];
            const float vz = raw0[bB * 25 + 8 + jB]  + raw1[bB * 25 + 8 + jB]  + bhs[8 + jB];
            const float vn = raw0[bB * 25 + 16 + jB] + raw1[bB * 25 + 16 + jB] + bhs[16 + jB];

            const float ahr = (vr - mu0) * r0 * ghs[jB]      + behs[jB];
            const float ahz = (vz - mu1) * r1 * ghs[8 + jB]  + behs[8 + jB];
            const float ahn = (vn - mu2) * r2 * ghs[16 + jB] + behs[16 + jB];

            const float r = 1.f / (1.f + __expf(-(axr + ahr)));
            const float z = 1.f / (1.f + __expf(-(axz + ahz)));
            const float n = tanhf(axn + r * ahn);
            const float hp = HROW(hsh, bB)[j0 + jB];
            const float hn = fmaf(z, hp - n, n);   // (1-z)*n + z*h

            g_h[(dir * 32 + bB) * 512 + j0 + jB] = hn;
            if (layer == 0) {
                g_seq[(size_t)dir * T_STEPS * 32 * 512
                      + ((size_t)tin * 32 + bB) * 512 + j0 + jB] = hn;
            } else {
                out[((size_t)tin * 32 + bB) * 1024 + dir * 512 + j0 + jB] = hn;
            }
            if (write_hid && s == T_STEPS - 1)
                out[(size_t)16777216 + ((size_t)wsel * 32 + bB) * 512 + j0 + jB] = hn;
        }
        bar_dir(ctr, target);   // h complete (own dir only)

        if (s + 1 < T_STEPS) {
            // h reload via cp.async.cg: all 16 copies in flight, no registers
#pragma unroll
            for (int r = 0; r < 16; ++r)
                CP_ASYNC16(hdst[r], hgsrc[r]);
            CP_COMMIT();
            CP_WAIT0();
            __syncthreads();
        }
    }
}

// ============================================================================
#define RS_BYTES ((24*WP + 32*HP + 2*800 + 24*3) * 4)

extern "C" void kernel_launch(void* const* d_in, const int* in_sizes, int n_in,
                              void* d_out, int out_size)
{
    const float* x   = (const float*)d_in[0];
    const float* h0  = (const float*)d_in[1];
    const float* Wx  = (const float*)d_in[2];
    const float* Wh  = (const float*)d_in[3];
    const float* bx  = (const float*)d_in[4];
    const float* bh  = (const float*)d_in[5];
    const float* gx  = (const float*)d_in[6];
    const float* bex = (const float*)d_in[7];
    const float* gh  = (const float*)d_in[8];
    const float* beh = (const float*)d_in[9];
    float* out = (float*)d_out;

    const int write_hid = (out_size >= 16777216 + 4 * 32 * 512) ? 1 : 0;

    cudaFuncSetAttribute(recurrent_kernel,
                         cudaFuncAttributeMaxDynamicSharedMemorySize, RS_BYTES);

    for (int layer = 0; layer < 2; ++layer) {
        dim3 gg(1536 / BN, 16384 / BM, 2);
        gemm_ax_kernel<<<gg, 512>>>(x, Wx, bx, layer);
        ln_ax_kernel<<<2 * 16384 * 3, 128>>>(gx, bex, layer);
        init_scratch_kernel<<<1, 256>>>();
        recurrent_kernel<<<NBLK, 256, RS_BYTES>>>(Wh, bh, gh, beh, h0, out,
                                                  layer, write_hid);
    }
}

// round 14
// speedup vs baseline: 1.6623x; 1.1282x over previous
#include <cuda_runtime.h>
#include <cstdint>

#define T_STEPS 512
#define BATCH   32
#define HID     512
#define LN_EPS  1e-5f
#define NBLK    128          // recurrent grid (64 CTAs per direction)
#define HP      544          // hsh pitch (floats); rows also per-row swizzled
#define WP      516          // Wsh pitch (floats)
#define RAWP    50           // raws row pitch

// ---- packed fp32x2 helpers (SASS FFMA2 — ptxas never auto-generates this) ----
#define FMA2(acc, a, b) \
    asm("fma.rn.f32x2 %0, %1, %2, %0;" : "+l"(acc) : "l"(a), "l"(b))

__device__ __forceinline__ float2 unpk(unsigned long long v) {
    float2 r;
    asm("mov.b64 {%0, %1}, %2;" : "=f"(r.x), "=f"(r.y) : "l"(v));
    return r;
}

// ---- acquire/release barrier primitives (no per-thread fences) --------------
__device__ __forceinline__ void red_rel_add(unsigned* p, unsigned v) {
    asm volatile("red.release.gpu.global.add.u32 [%0], %1;"
                 :: "l"(p), "r"(v) : "memory");
}
__device__ __forceinline__ unsigned ld_acq(const unsigned* p) {
    unsigned v;
    asm volatile("ld.acquire.gpu.global.u32 %0, [%1];"
                 : "=r"(v) : "l"(p) : "memory");
    return v;
}

// ---------------- scratch (static device globals; no allocation) ----------------
__device__ float    g_ax[(size_t)2 * 512 * 32 * 1536];   // LN(x@Wx+bx) per dir
__device__ float    g_seq[(size_t)2 * 512 * 32 * 512];   // layer-0 outputs (fwd, bwd)
__device__ float    g_h[2 * 32 * 512];                   // current hidden state per dir
__device__ float    g_part[2 * 32 * 3 * 2 * 32];         // [dir][b][g][st][colgrp]
__device__ unsigned g_barD[64];                          // per-dir counters (idx dir*32)

// ============================================================================
// Input GEMM: 128x128x16 fp32, 512 threads, 4x8 microtile via FFMA2. (UNCHANGED)
// ============================================================================
#define BM 128
#define BN 128
#define BK 16

__global__ __launch_bounds__(512)
void gemm_ax_kernel(const float* __restrict__ x,
                    const float* __restrict__ Wx,
                    const float* __restrict__ bx,
                    int layer)
{
    const int dir = blockIdx.z;
    const float* A = (layer == 0) ? x
                                  : (g_seq + (size_t)dir * T_STEPS * BATCH * HID);
    const int wsel = 2 * layer + dir;
    const float* Bw   = Wx + (size_t)wsel * 512 * 1536;
    const float* bias = bx + (size_t)wsel * 1536;
    float* C = g_ax + (size_t)dir * 16384 * 1536;

    const int m0 = blockIdx.y * BM;
    const int n0 = blockIdx.x * BN;

    __shared__ float As2[BK][2 * BM];
    __shared__ float Bs[BK][BN];

    const int tid = threadIdx.x;
    const int arow = tid & 127, akq = tid >> 7;
    const int bkr  = tid >> 5,  bcq = tid & 31;
    const int tx = tid & 15, rg = tid >> 4;

    unsigned long long acc2[4][4];
#pragma unroll
    for (int i = 0; i < 4; ++i)
#pragma unroll
        for (int j = 0; j < 4; ++j) acc2[i][j] = 0ull;

    for (int k0 = 0; k0 < 512; k0 += BK) {
        const float4 av = *(const float4*)(A + (size_t)(m0 + arow) * 512 + k0 + akq * 4);
        const float4 bv = *(const float4*)(Bw + (size_t)(k0 + bkr) * 1536 + n0 + bcq * 4);

        *(float2*)&As2[akq * 4 + 0][2 * arow] = make_float2(av.x, av.x);
        *(float2*)&As2[akq * 4 + 1][2 * arow] = make_float2(av.y, av.y);
        *(float2*)&As2[akq * 4 + 2][2 * arow] = make_float2(av.z, av.z);
        *(float2*)&As2[akq * 4 + 3][2 * arow] = make_float2(av.w, av.w);
        *(float4*)&Bs[bkr][bcq * 4] = bv;
        __syncthreads();

#pragma unroll
        for (int kk = 0; kk < BK; ++kk) {
            const ulonglong2 aL = *(const ulonglong2*)&As2[kk][rg * 8];
            const ulonglong2 aH = *(const ulonglong2*)&As2[kk][rg * 8 + 4];
            const ulonglong2 bL = *(const ulonglong2*)&Bs[kk][tx * 4];
            const ulonglong2 bH = *(const ulonglong2*)&Bs[kk][64 + tx * 4];
            const unsigned long long a[4] = {aL.x, aL.y, aH.x, aH.y};
            const unsigned long long b[4] = {bL.x, bL.y, bH.x, bH.y};
#pragma unroll
            for (int r = 0; r < 4; ++r) {
                FMA2(acc2[r][0], a[r], b[0]);
                FMA2(acc2[r][1], a[r], b[1]);
                FMA2(acc2[r][2], a[r], b[2]);
                FMA2(acc2[r][3], a[r], b[3]);
            }
        }
        __syncthreads();
    }

    const float4 bb0 = *(const float4*)(bias + n0 + tx * 4);
    const float4 bb1 = *(const float4*)(bias + n0 + 64 + tx * 4);
#pragma unroll
    for (int r = 0; r < 4; ++r) {
        const float2 u0 = unpk(acc2[r][0]), u1 = unpk(acc2[r][1]);
        const float2 u2 = unpk(acc2[r][2]), u3 = unpk(acc2[r][3]);
        const int row = m0 + rg * 4 + r;
        float4 o0 = make_float4(u0.x + bb0.x, u0.y + bb0.y, u1.x + bb0.z, u1.y + bb0.w);
        float4 o1 = make_float4(u2.x + bb1.x, u2.y + bb1.y, u3.x + bb1.z, u3.y + bb1.w);
        *(float4*)(C + (size_t)row * 1536 + n0 + tx * 4)      = o0;
        *(float4*)(C + (size_t)row * 1536 + n0 + 64 + tx * 4) = o1;
    }
}

// ============================================================================
// LayerNorm over each 512-wide gate chunk of g_ax (UNCHANGED).
// ============================================================================
__global__ void ln_ax_kernel(const float* __restrict__ gx,
                             const float* __restrict__ bex,
                             int layer)
{
    const int id   = blockIdx.x;
    const int gate = id % 3;
    const int row  = (id / 3) & 16383;
    const int dir  = id / (3 * 16384);
    const int wsel = 2 * layer + dir;

    float* p = g_ax + (size_t)dir * 16384 * 1536 + (size_t)row * 1536 + gate * 512;
    const float* gp = gx  + (size_t)wsel * 1536 + gate * 512;
    const float* bp = bex + (size_t)wsel * 1536 + gate * 512;

    const int tid = threadIdx.x;
    float4 v = *(const float4*)(p + tid * 4);
    float s  = v.x + v.y + v.z + v.w;
    float ss = v.x * v.x + v.y * v.y + v.z * v.z + v.w * v.w;
#pragma unroll
    for (int o = 16; o; o >>= 1) {
        s  += __shfl_xor_sync(0xffffffffu, s,  o);
        ss += __shfl_xor_sync(0xffffffffu, ss, o);
    }
    __shared__ float red[8];
    if ((tid & 31) == 0) { red[tid >> 5] = s; red[4 + (tid >> 5)] = ss; }
    __syncthreads();
    const float ts  = red[0] + red[1] + red[2] + red[3];
    const float tss = red[4] + red[5] + red[6] + red[7];
    const float mu   = ts * (1.f / 512.f);
    const float var  = tss * (1.f / 512.f) - mu * mu;
    const float rstd = rsqrtf(var + LN_EPS);

    const float4 g4 = *(const float4*)(gp + tid * 4);
    const float4 b4 = *(const float4*)(bp + tid * 4);
    float4 o;
    o.x = (v.x - mu) * rstd * g4.x + b4.x;
    o.y = (v.y - mu) * rstd * g4.y + b4.y;
    o.z = (v.z - mu) * rstd * g4.z + b4.z;
    o.w = (v.w - mu) * rstd * g4.w + b4.w;
    *(float4*)(p + tid * 4) = o;
}

// ============================================================================
__global__ void init_scratch_kernel()
{
    const int i = threadIdx.x;
    for (int k = i; k < 64; k += blockDim.x) g_barD[k] = 0u;
}

// ============================================================================
// Per-direction grid barrier (acquire/release, proven R10 design).
// ============================================================================
__device__ __forceinline__ void bar_dir(unsigned* ctr, unsigned& target)
{
    __syncthreads();                     // all CTA writes done (cta-scope rel)
    if (threadIdx.x == 0) {
        red_rel_add(ctr, 1u);            // release: publishes CTA's writes
        target += 64u;
        while (ld_acq(ctr) < target) { } // acquire: imports peers' writes
    }
    __syncthreads();                     // broadcast acquire to whole CTA
}

// h row pointer with per-row bank swizzle (b = LOCAL batch index 0..15).
#define HROW(hsh, b) ((hsh) + (b) * HP + ((((b) >> 1) & 7) << 2))

// ============================================================================
// Persistent recurrent kernel — R10 skeleton, ownership remapped to
// 16 batches x 48 weight-cols per CTA (was 32 x 24).
// ctaLoc = bg*32 + cg:  bg in {0,1} (batch half), cg in 0..31 (16-col group).
// Cuts per-step L2: h reload 64->32KB, partial table read 48->12KB.
// ============================================================================
__global__ __launch_bounds__(256)
void recurrent_kernel(const float* __restrict__ Wh,
                      const float* __restrict__ bh,
                      const float* __restrict__ gh,
                      const float* __restrict__ beh,
                      const float* __restrict__ h0,
                      float* __restrict__ out,
                      int layer, int write_hid)
{
    extern __shared__ float sm[];
    float* Wsh  = sm;                          // [48][WP] col-major    24768 f
    float* hsh  = Wsh + 48 * WP;               // [16][HP] swizzled      8704 f
    float* raw0 = hsh + 16 * HP;               // [16][RAWP] k-half 0     800 f
    float* raw1 = raw0 + 16 * RAWP;            // [16][RAWP] k-half 1     800 f
    float* bhs  = raw1 + 16 * RAWP;            // 48 f
    float* ghs  = bhs + 48;                    // 48 f
    float* behs = ghs + 48;                    // 48 f

    const int tid = threadIdx.x;
    const int cta = blockIdx.x;
    const int dir = cta >> 6;                  // 0 = fwd, 1 = bwd
    const int ctaLoc = cta & 63;
    const int bg = ctaLoc >> 5;                // batch half (0,1)
    const int cg = ctaLoc & 31;                // column group (16 cols)
    const int b0 = bg * 16;                    // global batch base
    const int j0 = cg * 16;                    // hidden-col base
    const int wsel = 2 * layer + dir;
    unsigned* ctr = g_barD + dir * 32;         // separate 128B lines per dir

    // ---- one-time loads ----
    // Wsh: 48 weight-cols (gate g = c>>4, hidden col j0 + (c&15)), col-major.
    const float* Whd = Wh + (size_t)wsel * 512 * 1536;
    for (int i = tid; i < 48 * 512; i += 256) {
        const int c = i >> 9, k = i & 511;
        const int col = ((c >> 4) << 9) + j0 + (c & 15);
        Wsh[c * WP + k] = Whd[(size_t)k * 1536 + col];
    }
    if (tid < 48) {
        const int col = ((tid >> 4) << 9) + j0 + (tid & 15);
        bhs[tid]  = bh [(size_t)wsel * 1536 + col];
        ghs[tid]  = gh [(size_t)wsel * 1536 + col];
        behs[tid] = beh[(size_t)wsel * 1536 + col];
    }
    // h: own 16 batches, full 512 k each.
    for (int i = tid; i < 16 * 128; i += 256) {
        const int b = i >> 7, q = i & 127;
        *(float4*)(HROW(hsh, b) + q * 4) =
            *(const float4*)(h0 + (size_t)wsel * 32 * 512 + (b0 + b) * 512 + q * 4);
    }
    __syncthreads();

    unsigned target = 0;
    // phase-A map: warp = (colQuad(2b), kHalf); lane = cgrp(2b) x bpair(3b)
    // thread: 3 wcols x 2 local batches x 256 k.
    const int warp = tid >> 5, lane = tid & 31;
    const int colQuad = warp & 3, kHalf = warp >> 2;
    const int cgrp = lane & 3, bpair = lane >> 2;
    const int c0  = (colQuad * 4 + cgrp) * 3;  // 3 wcols (0..45)
    const int bA0 = bpair * 2;                 // 2 local batches (0..14)
    const int kof = kHalf * 256;
    float* rawK = kHalf ? raw1 : raw0;
    // phase-B map: bB local 0..15, jB 0..15
    const int jB = tid & 15, bB = tid >> 4;

    const float* hr0 = HROW(hsh, bA0)     + kof;
    const float* hr1 = HROW(hsh, bA0 + 1) + kof;
    const float* w0 = Wsh + c0 * WP + kof;
    const float* w1 = w0 + WP;
    const float* w2 = w1 + WP;

    for (int s = 0; s < T_STEPS; ++s) {
        const int tin = dir ? (T_STEPS - 1 - s) : s;

        // prefetch ax for phase B (latency hides under phase-A GEMM)
        const float* axp = g_ax + (((size_t)dir * T_STEPS + tin) * 32 + b0 + bB) * 1536
                                + j0 + jB;
        const float axr = __ldg(axp);
        const float axz = __ldg(axp + 512);
        const float axn = __ldg(axp + 1024);

        // -------- Phase A: 2-batch x 3-col x 256-k GEMM via FFMA2 -----------
        {
            unsigned long long a00x=0,a00y=0,a01x=0,a01y=0;
            unsigned long long a10x=0,a10y=0,a11x=0,a11y=0;
            unsigned long long a20x=0,a20y=0,a21x=0,a21y=0;
#pragma unroll 8
            for (int k = 0; k < 256; k += 4) {
                const ulonglong2 ha = *(const ulonglong2*)(hr0 + k);
                const ulonglong2 hb = *(const ulonglong2*)(hr1 + k);
                const ulonglong2 wa = *(const ulonglong2*)(w0 + k);
                const ulonglong2 wb = *(const ulonglong2*)(w1 + k);
                const ulonglong2 wc = *(const ulonglong2*)(w2 + k);
                FMA2(a00x, ha.x, wa.x); FMA2(a00y, ha.y, wa.y);
                FMA2(a01x, hb.x, wa.x); FMA2(a01y, hb.y, wa.y);
                FMA2(a10x, ha.x, wb.x); FMA2(a10y, ha.y, wb.y);
                FMA2(a11x, hb.x, wb.x); FMA2(a11y, hb.y, wb.y);
                FMA2(a20x, ha.x, wc.x); FMA2(a20y, ha.y, wc.y);
                FMA2(a21x, hb.x, wc.x); FMA2(a21y, hb.y, wc.y);
            }
            float2 u, v;
            float* rpa = rawK + bA0 * RAWP + c0;
            float* rpb = rawK + (bA0 + 1) * RAWP + c0;
            u = unpk(a00x); v = unpk(a00y); rpa[0] = u.x + u.y + v.x + v.y;
            u = unpk(a10x); v = unpk(a10y); rpa[1] = u.x + u.y + v.x + v.y;
            u = unpk(a20x); v = unpk(a20y); rpa[2] = u.x + u.y + v.x + v.y;
            u = unpk(a01x); v = unpk(a01y); rpb[0] = u.x + u.y + v.x + v.y;
            u = unpk(a11x); v = unpk(a11y); rpb[1] = u.x + u.y + v.x + v.y;
            u = unpk(a21x); v = unpk(a21y); rpb[2] = u.x + u.y + v.x + v.y;
        }
        __syncthreads();

        // ---- LN stats partials: 48 threads (16 b x 3 g), plain stores ------
        if (tid < 48) {
            const int g = tid >> 4, b = tid & 15;
            const float* r0 = raw0 + b * RAWP + g * 16;
            const float* r1 = raw1 + b * RAWP + g * 16;
            const float* bb = bhs + g * 16;
            float sum = 0.f, sq = 0.f;
#pragma unroll
            for (int i = 0; i < 16; ++i) {
                const float v = r0[i] + r1[i] + bb[i];
                sum += v; sq += v * v;
            }
            const int base = (((dir * 32 + b0 + b) * 3 + g) * 2) * 32 + cg;
            g_part[base]      = sum;
            g_part[base + 32] = sq;
        }
        bar_dir(ctr, target);   // stats complete (own dir only)

        // -------- Phase B: reduce partials, gates, h_new --------------------
        {
            // per (b,g,st): 32 partials; 8 quarters of 4; jB&7 picks quarter,
            // shfl over offsets 1,2,4 combines (8-lane groups are aligned).
            const float* pb = g_part + (size_t)((dir * 32 + b0 + bB) * 3) * 2 * 32
                            + (jB & 7) * 4;
            float tot[6];
#pragma unroll
            for (int g = 0; g < 3; ++g)
#pragma unroll
                for (int st = 0; st < 2; ++st) {
                    const float4 u0 = __ldcg((const float4*)(pb + (g * 2 + st) * 32));
                    tot[g * 2 + st] = u0.x + u0.y + u0.z + u0.w;
                }
#pragma unroll
            for (int o = 1; o < 8; o <<= 1)
#pragma unroll
                for (int t = 0; t < 6; ++t)
                    tot[t] += __shfl_xor_sync(0xffffffffu, tot[t], o);

            const float mu0 = tot[0] * (1.f / 512.f);
            const float mu1 = tot[2] * (1.f / 512.f);
            const float mu2 = tot[4] * (1.f / 512.f);
            const float r0 = rsqrtf(tot[1] * (1.f / 512.f) - mu0 * mu0 + LN_EPS);
            const float r1 = rsqrtf(tot[3] * (1.f / 512.f) - mu1 * mu1 + LN_EPS);
            const float r2 = rsqrtf(tot[5] * (1.f / 512.f) - mu2 * mu2 + LN_EPS);

            const int off = bB * RAWP;
            const float vr = raw0[off + jB]      + raw1[off + jB]      + bhs[jB];
            const float vz = raw0[off + 16 + jB] + raw1[off + 16 + jB] + bhs[16 + jB];
            const float vn = raw0[off + 32 + jB] + raw1[off + 32 + jB] + bhs[32 + jB];

            const float ahr = (vr - mu0) * r0 * ghs[jB]      + behs[jB];
            const float ahz = (vz - mu1) * r1 * ghs[16 + jB] + behs[16 + jB];
            const float ahn = (vn - mu2) * r2 * ghs[32 + jB] + behs[32 + jB];

            const float r = 1.f / (1.f + __expf(-(axr + ahr)));
            const float z = 1.f / (1.f + __expf(-(axz + ahz)));
            const float n = tanhf(axn + r * ahn);
            const float hp = HROW(hsh, bB)[j0 + jB];
            const float hn = fmaf(z, hp - n, n);   // (1-z)*n + z*h

            g_h[(dir * 32 + b0 + bB) * 512 + j0 + jB] = hn;
            if (layer == 0) {
                g_seq[(size_t)dir * T_STEPS * 32 * 512
                      + ((size_t)tin * 32 + b0 + bB) * 512 + j0 + jB] = hn;
            } else {
                out[((size_t)tin * 32 + b0 + bB) * 1024 + dir * 512 + j0 + jB] = hn;
            }
            if (write_hid && s == T_STEPS - 1)
                out[(size_t)16777216 + ((size_t)wsel * 32 + b0 + bB) * 512 + j0 + jB] = hn;
        }
        bar_dir(ctr, target);   // h complete (own dir only)

        if (s + 1 < T_STEPS) {
            // reload own 16 batches only: 32 KB (2048 float4, 8 per thread)
            const float* hg = g_h + (dir * 32 + b0) * 512;
#pragma unroll
            for (int p = 0; p < 8; ++p) {
                const int i = tid + p * 256;
                const int b = i >> 7, q = i & 127;
                const float4 v = __ldcg((const float4*)(hg + b * 512 + q * 4));
                *(float4*)(HROW(hsh, b) + q * 4) = v;
            }
            __syncthreads();
        }
    }
}

// ============================================================================
#define RS_BYTES ((48*WP + 16*HP + 2*16*RAWP + 48*3) * 4)

extern "C" void kernel_launch(void* const* d_in, const int* in_sizes, int n_in,
                              void* d_out, int out_size)
{
    const float* x   = (const float*)d_in[0];
    const float* h0  = (const float*)d_in[1];
    const float* Wx  = (const float*)d_in[2];
    const float* Wh  = (const float*)d_in[3];
    const float* bx  = (const float*)d_in[4];
    const float* bh  = (const float*)d_in[5];
    const float* gx  = (const float*)d_in[6];
    const float* bex = (const float*)d_in[7];
    const float* gh  = (const float*)d_in[8];
    const float* beh = (const float*)d_in[9];
    float* out = (float*)d_out;

    const int write_hid = (out_size >= 16777216 + 4 * 32 * 512) ? 1 : 0;

    cudaFuncSetAttribute(recurrent_kernel,
                         cudaFuncAttributeMaxDynamicSharedMemorySize, RS_BYTES);

    for (int layer = 0; layer < 2; ++layer) {
        dim3 gg(1536 / BN, 16384 / BM, 2);
        gemm_ax_kernel<<<gg, 512>>>(x, Wx, bx, layer);
        ln_ax_kernel<<<2 * 16384 * 3, 128>>>(gx, bex, layer);
        init_scratch_kernel<<<1, 256>>>();
        recurrent_kernel<<<NBLK, 256, RS_BYTES>>>(Wh, bh, gh, beh, h0, out,
                                                  layer, write_hid);
    }
}